// round 5
// baseline (speedup 1.0000x reference)
#include <cuda_runtime.h>
#include <cuda_bf16.h>
#include <cstdint>

// Problem shape (fixed by the dataset)
static constexpr int B  = 4;
static constexpr int S  = 4096;
static constexpr int D  = 4096;
static constexpr int D4 = D / 4;             // 1024 float4 per (b, s) row

// Tiling
static constexpr int L     = 64;             // s-steps per chunk
static constexpr int C     = S / L;          // 64 chunks along S (fits 64-bit mask)
static constexpr int CH    = 16;             // float4 channel-groups per block (=64 scalar channels)
static constexpr int SEG   = 16;             // s-segments per chunk within a block
static constexpr int STEPS = L / SEG;        // 4 steps per thread
static constexpr int TD    = CH * SEG;       // 256 threads
static constexpr int NT    = (B * D4) / CH;  // 256 row tiles

static_assert(C <= 64, "chunk mask must fit in 64 bits");

// Scratch (static device globals — no dynamic allocation allowed)
__device__ float4             g_aggA[NT * C * CH];  // chunk aggregate A (gate product)
__device__ float4             g_aggB[NT * C * CH];  // chunk aggregate B (local scan tail)
__device__ unsigned long long g_mask[NT];           // per-tile publish bitmask

__device__ __forceinline__ float4 f4_fma(float4 a, float4 b, float4 c) {
    return make_float4(fmaf(a.x, b.x, c.x), fmaf(a.y, b.y, c.y),
                       fmaf(a.z, b.z, c.z), fmaf(a.w, b.w, c.w));
}
__device__ __forceinline__ float4 f4_mul(float4 a, float4 b) {
    return make_float4(a.x * b.x, a.y * b.y, a.z * b.z, a.w * b.w);
}

__global__ void __launch_bounds__(TD, 3)
assoc_scan_kernel(const float4* __restrict__ gates,
                  const float4* __restrict__ inputs,
                  const float4* __restrict__ prev,
                  float4* __restrict__ out)
{
    const int c   = blockIdx.x;          // chunk along S (fastest -> predecessors earlier/co-resident)
    const int y   = blockIdx.y;          // row tile
    const int t   = threadIdx.x;
    const int gi  = t % CH;              // channel-group within tile
    const int seg = t / CH;              // s-segment within chunk

    const int g    = y * CH + gi;        // global float4 channel-group
    const int b    = g / D4;
    const int col4 = g % D4;

    const size_t base = (size_t)b * S * D4 + (size_t)(c * L + seg * STEPS) * D4 + col4;

    // ---- Phase 1: bulk vectorized load (streaming, fully coalesced) ----
    float4 a[STEPS], v[STEPS];
#pragma unroll
    for (int i = 0; i < STEPS; i++) a[i] = __ldcs(&gates[base + (size_t)i * D4]);
#pragma unroll
    for (int i = 0; i < STEPS; i++) v[i] = __ldcs(&inputs[base + (size_t)i * D4]);

    const float4 pv = prev[(size_t)b * D4 + col4];

    // ---- Phase 2: local scan within segment ----
#pragma unroll
    for (int i = 1; i < STEPS; i++) {
        v[i] = f4_fma(a[i], v[i - 1], v[i]);
        a[i] = f4_mul(a[i], a[i - 1]);
    }

    __shared__ float4 shA[SEG][CH];
    __shared__ float4 shB[SEG][CH];
    __shared__ float4 sh_sin[CH];

    // ---- Phase 3: intra-chunk exclusive prefix over segments ----
    shA[seg][gi] = a[STEPS - 1];
    shB[seg][gi] = v[STEPS - 1];
    __syncthreads();

    float4 PA = make_float4(1.f, 1.f, 1.f, 1.f);
    float4 PB = make_float4(0.f, 0.f, 0.f, 0.f);
#pragma unroll
    for (int j = 0; j < SEG; j++) {      // P_seg = f_{seg-1} ∘ ... ∘ f_0
        if (j < seg) {
            const float4 Aj = shA[j][gi];
            const float4 Bj = shB[j][gi];
            PB = f4_fma(Aj, PB, Bj);
            PA = f4_mul(Aj, PA);
        }
    }

    // ---- Phase 4: publish chunk aggregate (f_last ∘ P_last, by last segment) ----
    if (c < C - 1) {
        if (seg == SEG - 1) {
            const float4 CA = f4_mul(a[STEPS - 1], PA);
            const float4 CB = f4_fma(a[STEPS - 1], PB, v[STEPS - 1]);
            const int aidx = (y * C + c) * CH + gi;
            g_aggA[aidx] = CA;
            g_aggB[aidx] = CB;
            __threadfence();             // release: aggregates visible before mask bit
        }
        __syncthreads();
        if (t == 0) atomicOr(&g_mask[y], 1ull << c);
    }

    // ---- Phase 5: resolve incoming state (sliced parallel fold over predecessors) ----
    float4 sin_;
    if (c == 0) {
        sin_ = pv;
    } else {
        if (t == 0) {
            const unsigned long long need = (1ull << c) - 1ull;
            while ((atomicOr(&g_mask[y], 0ull) & need) != need) __nanosleep(40);
        }
        __syncthreads();
        __threadfence();                 // acquire: order aggregate reads after flag

        // Each segment folds a contiguous slice of [0, c), newest-first within slice.
        const int len = (c + SEG - 1) / SEG;
        const int lo  = seg * len;
        const int hi  = min(lo + len, c);
        float4 FA = make_float4(1.f, 1.f, 1.f, 1.f);
        float4 FB = make_float4(0.f, 0.f, 0.f, 0.f);
        for (int j = hi - 1; j >= lo; j--) {
            const int jidx = (y * C + j) * CH + gi;
            const float4 Aj = __ldcg(&g_aggA[jidx]);
            const float4 Bj = __ldcg(&g_aggB[jidx]);
            FB = f4_fma(FA, Bj, FB);     // acc = acc ∘ f_j
            FA = f4_mul(FA, Aj);
        }

        shA[seg][gi] = FA;               // safe: __syncthreads above separates readers
        shB[seg][gi] = FB;
        __syncthreads();

        if (seg == 0) {                  // combine slice-partials oldest -> newest
            float4 TA = make_float4(1.f, 1.f, 1.f, 1.f);
            float4 TB = make_float4(0.f, 0.f, 0.f, 0.f);
#pragma unroll
            for (int k = 0; k < SEG; k++) {
                const float4 Ak = shA[k][gi];
                const float4 Bk = shB[k][gi];
                TB = f4_fma(Ak, TB, Bk); // total = G_k ∘ total
                TA = f4_mul(Ak, TA);
            }
            sh_sin[gi] = f4_fma(TA, pv, TB);
        }
        __syncthreads();
        sin_ = sh_sin[gi];
    }

    // ---- Phase 6: fix up and store (vectorized streaming) ----
    const float4 ss = f4_fma(PA, sin_, PB);   // state at the start of this segment
#pragma unroll
    for (int i = 0; i < STEPS; i++) {
        __stcs(&out[base + (size_t)i * D4], f4_fma(a[i], ss, v[i]));
    }
}

extern "C" void kernel_launch(void* const* d_in, const int* in_sizes, int n_in,
                              void* d_out, int out_size)
{
    const float4* gates  = (const float4*)d_in[0];
    const float4* inputs = (const float4*)d_in[1];
    const float4* prev   = (const float4*)d_in[2];
    float4* out          = (float4*)d_out;

    // Reset publish bitmasks (graph-capturable async memset on stream 0)
    void* mask_ptr = nullptr;
    cudaGetSymbolAddress(&mask_ptr, g_mask);
    cudaMemsetAsync(mask_ptr, 0, NT * sizeof(unsigned long long));

    dim3 grid(C, NT);   // chunk fastest -> predecessors co-resident / earlier waves
    dim3 block(TD);
    assoc_scan_kernel<<<grid, block>>>(gates, inputs, prev, out);
}

// round 6
// speedup vs baseline: 1.5286x; 1.5286x over previous
#include <cuda_runtime.h>
#include <cuda_bf16.h>
#include <cstdint>

// Problem shape (fixed by the dataset)
static constexpr int B  = 4;
static constexpr int S  = 4096;
static constexpr int D  = 4096;
static constexpr int D4 = D / 4;             // 1024 float4 per (b, s) row

// Tiling: each block owns CH float4-channels for the FULL sequence.
static constexpr int CH    = 16;             // float4 channel-groups per block (64 scalar channels)
static constexpr int SEG   = 16;             // s-segments per chunk
static constexpr int STEPS = 4;              // s-steps per thread per chunk
static constexpr int L     = SEG * STEPS;    // 64 s-steps per chunk
static constexpr int C     = S / L;          // 64 chunks, processed serially per block
static constexpr int TD    = CH * SEG;       // 256 threads
static constexpr int NB    = (B * D4) / CH;  // 256 blocks (single wave)

__device__ __forceinline__ float4 f4_fma(float4 a, float4 b, float4 c) {
    return make_float4(fmaf(a.x, b.x, c.x), fmaf(a.y, b.y, c.y),
                       fmaf(a.z, b.z, c.z), fmaf(a.w, b.w, c.w));
}
__device__ __forceinline__ float4 f4_mul(float4 a, float4 b) {
    return make_float4(a.x * b.x, a.y * b.y, a.z * b.z, a.w * b.w);
}

struct Smem {
    float4 shA[SEG][CH];
    float4 shB[SEG][CH];
};

__device__ __forceinline__ void load_chunk(const float4* __restrict__ gates,
                                           const float4* __restrict__ inputs,
                                           size_t base,
                                           float4 (&a)[STEPS], float4 (&v)[STEPS])
{
#pragma unroll
    for (int i = 0; i < STEPS; i++) a[i] = __ldcs(&gates[base + (size_t)i * D4]);
#pragma unroll
    for (int i = 0; i < STEPS; i++) v[i] = __ldcs(&inputs[base + (size_t)i * D4]);
}

// Process one resident chunk: local scan, segment prefix via smem, store, carry update.
__device__ __forceinline__ void process_chunk(float4 (&a)[STEPS], float4 (&v)[STEPS],
                                              size_t base, float4& carry,
                                              float4* __restrict__ out,
                                              Smem& sm, int seg, int gi)
{
    // Local scan within segment: a -> cumulative gate product, v -> zero-init scan.
#pragma unroll
    for (int i = 1; i < STEPS; i++) {
        v[i] = f4_fma(a[i], v[i - 1], v[i]);
        a[i] = f4_mul(a[i], a[i - 1]);
    }

    __syncthreads();                       // prior chunk's smem reads complete
    sm.shA[seg][gi] = a[STEPS - 1];
    sm.shB[seg][gi] = v[STEPS - 1];
    __syncthreads();

    // P = exclusive prefix over segments (f_{seg-1}∘..∘f_0); T = total (all SEG).
    float4 PA = make_float4(1.f, 1.f, 1.f, 1.f);
    float4 PB = make_float4(0.f, 0.f, 0.f, 0.f);
    float4 TA = make_float4(1.f, 1.f, 1.f, 1.f);
    float4 TB = make_float4(0.f, 0.f, 0.f, 0.f);
#pragma unroll
    for (int j = 0; j < SEG; j++) {
        const float4 Aj = sm.shA[j][gi];
        const float4 Bj = sm.shB[j][gi];
        if (j < seg) {                     // predicated; T independent of seg
            PB = f4_fma(Aj, PB, Bj);
            PA = f4_mul(Aj, PA);
        }
        TB = f4_fma(Aj, TB, Bj);
        TA = f4_mul(Aj, TA);
    }

    // State at segment start, then fix up and store.
    const float4 ss = f4_fma(PA, carry, PB);
#pragma unroll
    for (int i = 0; i < STEPS; i++) {
        __stcs(&out[base + (size_t)i * D4], f4_fma(a[i], ss, v[i]));
    }

    // Carry across chunk boundary (replicated identically in every thread).
    carry = f4_fma(TA, carry, TB);
}

__global__ void __launch_bounds__(TD, 2)
assoc_scan_kernel(const float4* __restrict__ gates,
                  const float4* __restrict__ inputs,
                  const float4* __restrict__ prev,
                  float4* __restrict__ out)
{
    const int t   = threadIdx.x;
    const int gi  = t % CH;                // channel-group within block
    const int seg = t / CH;                // s-segment within chunk

    const int g    = blockIdx.x * CH + gi; // global float4 channel-group
    const int b    = g / D4;
    const int col4 = g % D4;

    const size_t row    = (size_t)b * S * D4 + col4;
    const size_t segoff = (size_t)(seg * STEPS) * D4;
    const size_t cstep  = (size_t)L * D4;  // advance one chunk along S

    __shared__ Smem sm;

    float4 carry = prev[(size_t)b * D4 + col4];

    float4 a0[STEPS], v0[STEPS], a1[STEPS], v1[STEPS];

    // Prime the pipeline with chunk 0.
    load_chunk(gates, inputs, row + segoff, a0, v0);

#pragma unroll 1
    for (int c = 0; c < C; c += 2) {
        const size_t b0 = row + segoff + (size_t)c * cstep;
        const size_t b1 = b0 + cstep;

        // Prefetch chunk c+1 while chunk c computes.
        if (c + 1 < C) load_chunk(gates, inputs, b1, a1, v1);
        process_chunk(a0, v0, b0, carry, out, sm, seg, gi);

        // Prefetch chunk c+2 while chunk c+1 computes.
        if (c + 2 < C) load_chunk(gates, inputs, b1 + cstep, a0, v0);
        if (c + 1 < C) process_chunk(a1, v1, b1, carry, out, sm, seg, gi);
    }
}

extern "C" void kernel_launch(void* const* d_in, const int* in_sizes, int n_in,
                              void* d_out, int out_size)
{
    const float4* gates  = (const float4*)d_in[0];
    const float4* inputs = (const float4*)d_in[1];
    const float4* prev   = (const float4*)d_in[2];
    float4* out          = (float4*)d_out;

    assoc_scan_kernel<<<NB, TD>>>(gates, inputs, prev, out);
}

// round 7
// speedup vs baseline: 1.7004x; 1.1124x over previous
#include <cuda_runtime.h>
#include <cuda_bf16.h>
#include <cstdint>

// Problem shape (fixed by the dataset)
static constexpr int B  = 4;
static constexpr int S  = 4096;
static constexpr int D  = 4096;
static constexpr int D4 = D / 4;             // 1024 float4 per (b, s) row

// Tiling: each block owns CH float4-channels for the FULL sequence.
static constexpr int CH    = 16;             // float4 channel-groups per block (64 scalar channels)
static constexpr int SEG   = 16;             // s-segments per chunk
static constexpr int STEPS = 4;              // s-steps per thread per chunk
static constexpr int L     = SEG * STEPS;    // 64 s-steps per chunk
static constexpr int C     = S / L;          // 64 chunks, processed serially per block
static constexpr int TD    = CH * SEG;       // 256 threads
static constexpr int NB    = (B * D4) / CH;  // 256 blocks (single wave)

__device__ __forceinline__ float4 f4_fma(float4 a, float4 b, float4 c) {
    return make_float4(fmaf(a.x, b.x, c.x), fmaf(a.y, b.y, c.y),
                       fmaf(a.z, b.z, c.z), fmaf(a.w, b.w, c.w));
}
__device__ __forceinline__ float4 f4_mul(float4 a, float4 b) {
    return make_float4(a.x * b.x, a.y * b.y, a.z * b.z, a.w * b.w);
}

struct Smem {
    float4 shA[2][SEG][CH];   // parity-buffered segment aggregates (gate products)
    float4 shB[2][SEG][CH];   // parity-buffered segment aggregates (scan tails)
    float4 shC[2][CH];        // parity-buffered inter-chunk carry broadcast
};

__device__ __forceinline__ void load_chunk(const float4* __restrict__ gates,
                                           const float4* __restrict__ inputs,
                                           size_t base,
                                           float4 (&a)[STEPS], float4 (&v)[STEPS])
{
#pragma unroll
    for (int i = 0; i < STEPS; i++) a[i] = __ldcs(&gates[base + (size_t)i * D4]);
#pragma unroll
    for (int i = 0; i < STEPS; i++) v[i] = __ldcs(&inputs[base + (size_t)i * D4]);
}

// Process one resident chunk. P = compile-time parity. ONE barrier per chunk.
template <int P>
__device__ __forceinline__ void process_chunk(float4 (&a)[STEPS], float4 (&v)[STEPS],
                                              size_t base,
                                              float4* __restrict__ out,
                                              Smem& sm, int seg, int gi)
{
    // Local scan within segment: a -> cumulative gate product, v -> zero-init scan.
#pragma unroll
    for (int i = 1; i < STEPS; i++) {
        v[i] = f4_fma(a[i], v[i - 1], v[i]);
        a[i] = f4_mul(a[i], a[i - 1]);
    }

    // Publish segment aggregate into this chunk's parity buffer.
    sm.shA[P][seg][gi] = a[STEPS - 1];
    sm.shB[P][seg][gi] = v[STEPS - 1];
    __syncthreads();   // orders: this write -> all reads below; prev-chunk carry write -> read

    // Carry entering this chunk (broadcast by last chunk's seg-15 threads, or seeded pv).
    const float4 cv = sm.shC[P ^ 1][gi];

    // Exclusive prefix over earlier segments only (avg SEG/2 iterations).
    float4 PA = make_float4(1.f, 1.f, 1.f, 1.f);
    float4 PB = make_float4(0.f, 0.f, 0.f, 0.f);
    for (int j = 0; j < seg; j++) {
        const float4 Aj = sm.shA[P][j][gi];
        const float4 Bj = sm.shB[P][j][gi];
        PB = f4_fma(Aj, PB, Bj);
        PA = f4_mul(Aj, PA);
    }

    // State at segment start.
    const float4 ss = f4_fma(PA, cv, PB);

    // Last segment broadcasts next chunk's carry (read after NEXT chunk's barrier).
    if (seg == SEG - 1) {
        sm.shC[P][gi] = f4_fma(a[STEPS - 1], ss, v[STEPS - 1]);
    }

    // Fix up and store (vectorized streaming).
#pragma unroll
    for (int i = 0; i < STEPS; i++) {
        __stcs(&out[base + (size_t)i * D4], f4_fma(a[i], ss, v[i]));
    }
}

__global__ void __launch_bounds__(TD, 2)
assoc_scan_kernel(const float4* __restrict__ gates,
                  const float4* __restrict__ inputs,
                  const float4* __restrict__ prev,
                  float4* __restrict__ out)
{
    const int t   = threadIdx.x;
    const int gi  = t % CH;                // channel-group within block
    const int seg = t / CH;                // s-segment within chunk

    const int g    = blockIdx.x * CH + gi; // global float4 channel-group
    const int b    = g / D4;
    const int col4 = g % D4;

    const size_t row    = (size_t)b * S * D4 + col4;
    const size_t segoff = (size_t)(seg * STEPS) * D4;
    const size_t cstep  = (size_t)L * D4;  // advance one chunk along S

    __shared__ Smem sm;

    // Seed the carry pipeline: chunk 0 (parity 0) reads shC[1].
    if (seg == SEG - 1) {
        sm.shC[1][gi] = prev[(size_t)b * D4 + col4];
    }
    // (ordered before chunk 0's reads by chunk 0's own __syncthreads)

    float4 a0[STEPS], v0[STEPS], a1[STEPS], v1[STEPS];

    // Prime the pipeline with chunk 0.
    load_chunk(gates, inputs, row + segoff, a0, v0);

#pragma unroll 1
    for (int c = 0; c < C; c += 2) {
        const size_t b0 = row + segoff + (size_t)c * cstep;
        const size_t b1 = b0 + cstep;

        // Prefetch chunk c+1 while chunk c computes.
        if (c + 1 < C) load_chunk(gates, inputs, b1, a1, v1);
        process_chunk<0>(a0, v0, b0, out, sm, seg, gi);

        // Prefetch chunk c+2 while chunk c+1 computes.
        if (c + 2 < C) load_chunk(gates, inputs, b1 + cstep, a0, v0);
        if (c + 1 < C) process_chunk<1>(a1, v1, b1, out, sm, seg, gi);
    }
}

extern "C" void kernel_launch(void* const* d_in, const int* in_sizes, int n_in,
                              void* d_out, int out_size)
{
    const float4* gates  = (const float4*)d_in[0];
    const float4* inputs = (const float4*)d_in[1];
    const float4* prev   = (const float4*)d_in[2];
    float4* out          = (float4*)d_out;

    assoc_scan_kernel<<<NB, TD>>>(gates, inputs, prev, out);
}